// round 15
// baseline (speedup 1.0000x reference)
#include <cuda_runtime.h>
#include <cuda_bf16.h>
#include <cstdint>

#define N_NODES 100000
#define N_EDGES 600000
#define N_GRAPHS 512
#define DIM 128
#define N_LAYERS 3
#define BN_EPS 1e-5f

// ---------------- scratch (device globals; no allocation allowed) ----------
__device__ __align__(16) float g_AGG[(size_t)N_NODES * DIM];
__device__ __align__(16) float g_T[(size_t)N_NODES * DIM];
__device__ float g_S1[DIM], g_Q1[DIM], g_S2[DIM], g_Q2[DIM];
__device__ int g_gstart[N_GRAPHS + 1];
// W fragments, interleaved {hi0,hi1,lo0,lo1}: [mat][kb 8][nb 16][lane 32][4]
__device__ __align__(16) uint32_t g_Wfrag[6 * 16384];

// ---------------- helpers ----------------------------------------------------
__device__ __forceinline__ uint32_t pack_bf16x2(float f0, float f1) {
    __nv_bfloat162 h = __floats2bfloat162_rn(f0, f1);
    return *reinterpret_cast<uint32_t*>(&h);
}
__device__ __forceinline__ void split2(float2 v, uint32_t& hi, uint32_t& lo) {
    __nv_bfloat16 h0 = __float2bfloat16_rn(v.x);
    __nv_bfloat16 h1 = __float2bfloat16_rn(v.y);
    float l0 = v.x - __bfloat162float(h0);
    float l1 = v.y - __bfloat162float(h1);
    __nv_bfloat162 hp; hp.x = h0; hp.y = h1;
    hi = *reinterpret_cast<uint32_t*>(&hp);
    lo = pack_bf16x2(l0, l1);
}
__device__ __forceinline__ void mma_bf16(float c[4], const uint32_t a[4], uint32_t b0, uint32_t b1) {
    asm volatile(
        "mma.sync.aligned.m16n8k16.row.col.f32.bf16.bf16.f32 "
        "{%0,%1,%2,%3}, {%4,%5,%6,%7}, {%8,%9}, {%0,%1,%2,%3};"
        : "+f"(c[0]), "+f"(c[1]), "+f"(c[2]), "+f"(c[3])
        : "r"(a[0]), "r"(a[1]), "r"(a[2]), "r"(a[3]), "r"(b0), "r"(b1));
}

// ---------------- prep: W split/layout + graph segment bounds ----------------
__global__ void prep_kernel(const float* __restrict__ W1, const float* __restrict__ W2,
                            const int* __restrict__ batch) {
    int idx = blockIdx.x * blockDim.x + threadIdx.x;
    if (idx < 6 * 4096) {
        int mat = idx >> 12;
        int e = idx & 4095;
        int lane = e & 31;
        int nb = (e >> 5) & 15;
        int kb = e >> 9;
        int n = nb * 8 + (lane >> 2);
        const float* W = (mat < 3) ? (W1 + (size_t)mat * 16384)
                                   : (W2 + (size_t)(mat - 3) * 16384);
        uint32_t hi0, lo0, hi1, lo1;
        int k0 = kb * 16 + (lane & 3) * 2;
        split2(make_float2(W[k0 * 128 + n], W[(k0 + 1) * 128 + n]), hi0, lo0);
        int k1 = k0 + 8;
        split2(make_float2(W[k1 * 128 + n], W[(k1 + 1) * 128 + n]), hi1, lo1);
        reinterpret_cast<uint4*>(g_Wfrag)[mat * 4096 + e] = make_uint4(hi0, hi1, lo0, lo1);
    }
    if (idx <= N_NODES) {
        int prev = (idx == 0) ? -1 : batch[idx - 1];
        int cur = (idx == N_NODES) ? N_GRAPHS : batch[idx];
        for (int g = prev + 1; g <= cur; g++) g_gstart[g] = idx;
    }
}

// ---------------- aggregation -------------------------------------------------
__global__ void copy_to_agg_kernel(const float* __restrict__ H) {
    int i = blockIdx.x * blockDim.x + threadIdx.x;
    if (i < N_NODES * (DIM / 4))
        reinterpret_cast<float4*>(g_AGG)[i] = reinterpret_cast<const float4*>(H)[i];
}

// AGG[dst] += H[src] — 4 independent edge-chunks per thread for MLP.
// Block 0 also zeroes the BN accumulators for this layer (runs before gemm<1>).
#define SCATTER_WORK (N_EDGES * 32)          // float4 chunks total
#define SCATTER_QTR (SCATTER_WORK / 4)
__global__ void scatter_add_kernel(const float* __restrict__ H,
                                   const int* __restrict__ src,
                                   const int* __restrict__ dst) {
    int idx = blockIdx.x * blockDim.x + threadIdx.x;
    if (blockIdx.x == 0 && threadIdx.x < DIM) {
        g_S1[threadIdx.x] = 0.f; g_Q1[threadIdx.x] = 0.f;
        g_S2[threadIdx.x] = 0.f; g_Q2[threadIdx.x] = 0.f;
    }
    if (idx >= SCATTER_QTR) return;
    const int j = idx & 31;
    int e0 = idx >> 5;
    int e1 = (idx + SCATTER_QTR) >> 5;
    int e2 = (idx + 2 * SCATTER_QTR) >> 5;
    int e3 = (idx + 3 * SCATTER_QTR) >> 5;
    int s0 = __ldg(&src[e0]), d0 = __ldg(&dst[e0]);
    int s1 = __ldg(&src[e1]), d1 = __ldg(&dst[e1]);
    int s2 = __ldg(&src[e2]), d2 = __ldg(&dst[e2]);
    int s3 = __ldg(&src[e3]), d3 = __ldg(&dst[e3]);
    float4 v0 = reinterpret_cast<const float4*>(H)[s0 * 32 + j];
    float4 v1 = reinterpret_cast<const float4*>(H)[s1 * 32 + j];
    float4 v2 = reinterpret_cast<const float4*>(H)[s2 * 32 + j];
    float4 v3 = reinterpret_cast<const float4*>(H)[s3 * 32 + j];
    atomicAdd(reinterpret_cast<float4*>(g_AGG) + d0 * 32 + j, v0);
    atomicAdd(reinterpret_cast<float4*>(g_AGG) + d1 * 32 + j, v1);
    atomicAdd(reinterpret_cast<float4*>(g_AGG) + d2 * 32 + j, v2);
    atomicAdd(reinterpret_cast<float4*>(g_AGG) + d3 * 32 + j, v3);
}

// ---------------- HMMA GEMM + column stats -----------------------------------
// PHASE 1: T   = AGG @ W + b    (stats -> S1/Q1)
// PHASE 2: AGG = BN1(T) @ W + b (BN1 from S1/Q1 in prologue; stats -> S2/Q2)
// Ping-pong buffers: NEVER in-place (cross-warp safe for the 32x64 tile).
// Block: 128 rows x 128 cols, 8 warps; warp = 32 rows x 64 cols
// (rg=wid&3 row group, ch=wid>>2 column half): each B fragment LDS feeds
// TWO row-block MMA triples -> half the LDS traffic vs 16x128 tile.
#define SMB_BFRAG 0
#define SMB_BIAS 65536
#define SMB_SCL 66048
#define SMB_SHF 66560
#define SMB_SS 67072
#define SMB_SQ 67584
#define SMB_TOTAL 68096

template <int PHASE>
__global__ void __launch_bounds__(256) gemm_mma_kernel(int mat,
                                                       const float* __restrict__ bias,
                                                       const float* __restrict__ bn_g,
                                                       const float* __restrict__ bn_b) {
    const float* A   = (PHASE == 1) ? g_AGG : g_T;
    float*       Out = (PHASE == 1) ? g_T : g_AGG;
    float*       Sg  = (PHASE == 1) ? g_S1 : g_S2;
    float*       Qg  = (PHASE == 1) ? g_Q1 : g_Q2;

    extern __shared__ __align__(16) char smem[];
    uint32_t* sBf  = reinterpret_cast<uint32_t*>(smem + SMB_BFRAG);
    float* sBias = reinterpret_cast<float*>(smem + SMB_BIAS);
    float* sScl  = reinterpret_cast<float*>(smem + SMB_SCL);
    float* sShf  = reinterpret_cast<float*>(smem + SMB_SHF);
    float* sS    = reinterpret_cast<float*>(smem + SMB_SS);
    float* sQ    = reinterpret_cast<float*>(smem + SMB_SQ);

    const int tid = threadIdx.x;
    const int wid = tid >> 5;
    const int lane = tid & 31;
    const int qrow = lane >> 2;
    const int qk = (lane & 3) * 2;
    const int rg = wid & 3;          // row group: 32 rows
    const int ch = wid >> 2;         // column half (0/1)
    const int row0 = blockIdx.x * 128;

    {
        const uint4* wf = reinterpret_cast<const uint4*>(g_Wfrag + mat * 16384);
        uint4* bf = reinterpret_cast<uint4*>(sBf);
#pragma unroll
        for (int i = 0; i < 16; i++) {
            int idx = tid + i * 256;
            bf[idx] = wf[idx];
        }
    }
    if (tid < DIM) {
        sBias[tid] = bias[tid];
        sS[tid] = 0.f; sQ[tid] = 0.f;
        if (PHASE == 2) {
            // BN1 fold: S1/Q1 are final after the gemm<1> kernel boundary
            const float invN = 1.0f / (float)N_NODES;
            float m = g_S1[tid] * invN;
            float v = fmaxf(g_Q1[tid] * invN - m * m, 0.f);
            float sc = rsqrtf(v + BN_EPS) * bn_g[tid];
            sScl[tid] = sc;
            sShf[tid] = bn_b[tid] - m * sc;
        }
    }
    __syncthreads();

    const int rbase = row0 + rg * 32 + qrow;
    const int r0 = rbase, r1 = rbase + 8, r2 = rbase + 16, r3 = rbase + 24;
    const bool v0 = (r0 < N_NODES), v1 = (r1 < N_NODES);
    const bool v2 = (r2 < N_NODES), v3 = (r3 < N_NODES);
    const float* a0p = A + (size_t)r0 * DIM;
    const float* a1p = A + (size_t)r1 * DIM;
    const float* a2p = A + (size_t)r2 * DIM;
    const float* a3p = A + (size_t)r3 * DIM;

    float c0[8][4], c1[8][4];
#pragma unroll
    for (int nb = 0; nb < 8; nb++) {
#pragma unroll
        for (int q = 0; q < 4; q++) { c0[nb][q] = 0.f; c1[nb][q] = 0.f; }
    }

    const float2 FZ = make_float2(0.f, 0.f);
#pragma unroll
    for (int kb = 0; kb < 8; kb++) {
        const int cidx = kb * 16 + qk;
        float2 x00 = FZ, x01 = FZ, x10 = FZ, x11 = FZ;
        float2 x20 = FZ, x21 = FZ, x30 = FZ, x31 = FZ;
        if (v0) { x00 = *reinterpret_cast<const float2*>(a0p + cidx);
                  x01 = *reinterpret_cast<const float2*>(a0p + cidx + 8); }
        if (v1) { x10 = *reinterpret_cast<const float2*>(a1p + cidx);
                  x11 = *reinterpret_cast<const float2*>(a1p + cidx + 8); }
        if (v2) { x20 = *reinterpret_cast<const float2*>(a2p + cidx);
                  x21 = *reinterpret_cast<const float2*>(a2p + cidx + 8); }
        if (v3) { x30 = *reinterpret_cast<const float2*>(a3p + cidx);
                  x31 = *reinterpret_cast<const float2*>(a3p + cidx + 8); }
        if (PHASE == 2) {
            const float s0_ = sScl[cidx],     h0_ = sShf[cidx];
            const float s1_ = sScl[cidx + 1], h1_ = sShf[cidx + 1];
            const float s8_ = sScl[cidx + 8], h8_ = sShf[cidx + 8];
            const float s9_ = sScl[cidx + 9], h9_ = sShf[cidx + 9];
            x00.x = fmaf(x00.x, s0_, h0_); x00.y = fmaf(x00.y, s1_, h1_);
            x01.x = fmaf(x01.x, s8_, h8_); x01.y = fmaf(x01.y, s9_, h9_);
            x10.x = fmaf(x10.x, s0_, h0_); x10.y = fmaf(x10.y, s1_, h1_);
            x11.x = fmaf(x11.x, s8_, h8_); x11.y = fmaf(x11.y, s9_, h9_);
            x20.x = fmaf(x20.x, s0_, h0_); x20.y = fmaf(x20.y, s1_, h1_);
            x21.x = fmaf(x21.x, s8_, h8_); x21.y = fmaf(x21.y, s9_, h9_);
            x30.x = fmaf(x30.x, s0_, h0_); x30.y = fmaf(x30.y, s1_, h1_);
            x31.x = fmaf(x31.x, s8_, h8_); x31.y = fmaf(x31.y, s9_, h9_);
        }
        uint32_t ahi0[4], alo0[4], ahi1[4], alo1[4];
        split2(x00, ahi0[0], alo0[0]);
        split2(x10, ahi0[1], alo0[1]);
        split2(x01, ahi0[2], alo0[2]);
        split2(x11, ahi0[3], alo0[3]);
        split2(x20, ahi1[0], alo1[0]);
        split2(x30, ahi1[1], alo1[1]);
        split2(x21, ahi1[2], alo1[2]);
        split2(x31, ahi1[3], alo1[3]);

#pragma unroll
        for (int nb = 0; nb < 8; nb++) {
            const int nbg = ch * 8 + nb;
            const uint4 b = *reinterpret_cast<const uint4*>(&sBf[((kb * 16 + nbg) * 32 + lane) * 4]);
            mma_bf16(c0[nb], ahi0, b.x, b.y);
            mma_bf16(c0[nb], ahi0, b.z, b.w);
            mma_bf16(c0[nb], alo0, b.x, b.y);
            mma_bf16(c1[nb], ahi1, b.x, b.y);
            mma_bf16(c1[nb], ahi1, b.z, b.w);
            mma_bf16(c1[nb], alo1, b.x, b.y);
        }
    }

    // ---- epilogue: bias + store + column stats ----
#pragma unroll
    for (int nb = 0; nb < 8; nb++) {
        const int cn = (ch * 8 + nb) * 8 + qk;
        const float b0 = sBias[cn], b1 = sBias[cn + 1];
        float o00 = v0 ? (c0[nb][0] + b0) : 0.f;
        float o01 = v0 ? (c0[nb][1] + b1) : 0.f;
        float o10 = v1 ? (c0[nb][2] + b0) : 0.f;
        float o11 = v1 ? (c0[nb][3] + b1) : 0.f;
        float o20 = v2 ? (c1[nb][0] + b0) : 0.f;
        float o21 = v2 ? (c1[nb][1] + b1) : 0.f;
        float o30 = v3 ? (c1[nb][2] + b0) : 0.f;
        float o31 = v3 ? (c1[nb][3] + b1) : 0.f;
        if (v0) *reinterpret_cast<float2*>(Out + (size_t)r0 * DIM + cn) = make_float2(o00, o01);
        if (v1) *reinterpret_cast<float2*>(Out + (size_t)r1 * DIM + cn) = make_float2(o10, o11);
        if (v2) *reinterpret_cast<float2*>(Out + (size_t)r2 * DIM + cn) = make_float2(o20, o21);
        if (v3) *reinterpret_cast<float2*>(Out + (size_t)r3 * DIM + cn) = make_float2(o30, o31);
        float s0 = o00 + o10 + o20 + o30;
        float s1 = o01 + o11 + o21 + o31;
        float q0 = o00 * o00 + o10 * o10 + o20 * o20 + o30 * o30;
        float q1 = o01 * o01 + o11 * o11 + o21 * o21 + o31 * o31;
#pragma unroll
        for (int off = 4; off < 32; off <<= 1) {
            s0 += __shfl_down_sync(0xFFFFFFFF, s0, off);
            s1 += __shfl_down_sync(0xFFFFFFFF, s1, off);
            q0 += __shfl_down_sync(0xFFFFFFFF, q0, off);
            q1 += __shfl_down_sync(0xFFFFFFFF, q1, off);
        }
        if (lane < 4) {
            atomicAdd(&sS[cn], s0);
            atomicAdd(&sS[cn + 1], s1);
            atomicAdd(&sQ[cn], q0);
            atomicAdd(&sQ[cn + 1], q1);
        }
    }
    __syncthreads();
    if (tid < DIM) { atomicAdd(&Sg[tid], sS[tid]); atomicAdd(&Qg[tid], sQ[tid]); }
}

// H = relu(AGG * sc2 + sh2), BN2∘BN3 coefficients computed in-block from S2/Q2.
// If WRITE_AGG also primes g_AGG = H for next layer.
template <bool WRITE_AGG>
__global__ void apply_relu_kernel(float* __restrict__ H,
                                  const float* __restrict__ g2,
                                  const float* __restrict__ go,
                                  const float* __restrict__ bo) {
    __shared__ float sc2[DIM], sh2[DIM];
    if (threadIdx.x < DIM) {
        int t = threadIdx.x;
        const float invN = 1.0f / (float)N_NODES;
        float m = g_S2[t] * invN;
        float v = fmaxf(g_Q2[t] * invN - m * m, 0.f);
        float r2 = rsqrtf(v + BN_EPS);
        float gg = g2[t];
        float vy = gg * gg * v * r2 * r2;            // exact var of BN2 output
        float sc3 = rsqrtf(vy + BN_EPS) * go[t];
        float total = r2 * gg * sc3;
        sc2[t] = total;
        sh2[t] = bo[t] - m * total;
    }
    __syncthreads();
    int i = blockIdx.x * blockDim.x + threadIdx.x;
    if (i >= N_NODES * (DIM / 4)) return;
    int k = (i & 31) * 4;
    float4 v = reinterpret_cast<float4*>(g_AGG)[i];
    v.x = fmaxf(fmaf(v.x, sc2[k + 0], sh2[k + 0]), 0.f);
    v.y = fmaxf(fmaf(v.y, sc2[k + 1], sh2[k + 1]), 0.f);
    v.z = fmaxf(fmaf(v.z, sc2[k + 2], sh2[k + 2]), 0.f);
    v.w = fmaxf(fmaf(v.w, sc2[k + 3], sh2[k + 3]), 0.f);
    reinterpret_cast<float4*>(H)[i] = v;
    if (WRITE_AGG) reinterpret_cast<float4*>(g_AGG)[i] = v;
}

// ---------------- pooling + classifier ---------------------------------------
__global__ void graph_fc_kernel(const float* __restrict__ H,
                                const float* __restrict__ fcW,
                                const float* __restrict__ fcb,
                                float* __restrict__ Gout,
                                float* __restrict__ Cout) {
    int g = blockIdx.x;
    int t = threadIdx.x;
    int beg = g_gstart[g], end = g_gstart[g + 1];
    float s = 0.f;
    for (int r = beg; r < end; r++) s += H[r * DIM + t];
    float cnt = fmaxf((float)(end - beg), 1.0f);
    float ge = s / cnt;
    Gout[g * DIM + t] = ge;
    __shared__ float r0[DIM], r1[DIM];
    r0[t] = ge * fcW[t * 2 + 0];
    r1[t] = ge * fcW[t * 2 + 1];
    __syncthreads();
    for (int sh = 64; sh > 0; sh >>= 1) {
        if (t < sh) { r0[t] += r0[t + sh]; r1[t] += r1[t + sh]; }
        __syncthreads();
    }
    if (t == 0) {
        Cout[g * 2 + 0] = r0[0] + fcb[0];
        Cout[g * 2 + 1] = r1[0] + fcb[1];
    }
}

// ---------------- launcher ---------------------------------------------------
extern "C" void kernel_launch(void* const* d_in, const int* in_sizes, int n_in,
                              void* d_out, int out_size) {
    const float* x     = (const float*)d_in[0];
    const int*   ei    = (const int*)d_in[1];
    const int*   batch = (const int*)d_in[2];
    const float* W1    = (const float*)d_in[3];
    const float* b1    = (const float*)d_in[4];
    const float* g1    = (const float*)d_in[5];
    const float* bt1   = (const float*)d_in[6];
    const float* W2    = (const float*)d_in[7];
    const float* b2    = (const float*)d_in[8];
    const float* g2    = (const float*)d_in[9];
    // d_in[10] (bt2) cancels analytically in BN2∘BN3
    const float* go    = (const float*)d_in[11];
    const float* bo    = (const float*)d_in[12];
    const float* fcW   = (const float*)d_in[13];
    const float* fcb   = (const float*)d_in[14];

    float* out  = (float*)d_out;
    float* Hout = out;
    float* Gout = out + (size_t)N_NODES * DIM;
    float* Cout = Gout + (size_t)N_GRAPHS * DIM;

    const int* src = ei;
    const int* dst = ei + N_EDGES;

    static bool attr_set = false;
    if (!attr_set) {
        cudaFuncSetAttribute(gemm_mma_kernel<1>, cudaFuncAttributeMaxDynamicSharedMemorySize, SMB_TOTAL);
        cudaFuncSetAttribute(gemm_mma_kernel<2>, cudaFuncAttributeMaxDynamicSharedMemorySize, SMB_TOTAL);
        attr_set = true;
    }

    const int nCopyBlocks    = (N_NODES * (DIM / 4)) / 256;      // 12500
    const int nScatterBlocks = (SCATTER_QTR + 255) / 256;        // 18750
    const int nGemmBlocks    = (N_NODES + 127) / 128;            // 782

    prep_kernel<<<(N_NODES + 256) / 256, 256>>>(W1, W2, batch);

    for (int i = 0; i < N_LAYERS; i++) {
        const float* Hin = (i == 0) ? x : Hout;
        if (i == 0) copy_to_agg_kernel<<<nCopyBlocks, 256>>>(Hin);
        scatter_add_kernel<<<nScatterBlocks, 256>>>(Hin, src, dst);
        gemm_mma_kernel<1><<<nGemmBlocks, 256, SMB_TOTAL>>>(i, b1 + i * DIM,
                                                            nullptr, nullptr);
        gemm_mma_kernel<2><<<nGemmBlocks, 256, SMB_TOTAL>>>(i + 3, b2 + i * DIM,
                                                            g1 + i * DIM, bt1 + i * DIM);
        if (i + 1 < N_LAYERS)
            apply_relu_kernel<true><<<nCopyBlocks, 256>>>(Hout, g2 + i * DIM,
                                                          go + i * DIM, bo + i * DIM);
        else
            apply_relu_kernel<false><<<nCopyBlocks, 256>>>(Hout, g2 + i * DIM,
                                                           go + i * DIM, bo + i * DIM);
    }

    graph_fc_kernel<<<N_GRAPHS, 128>>>(Hout, fcW, fcb, Gout, Cout);
}

// round 16
// speedup vs baseline: 1.2662x; 1.2662x over previous
#include <cuda_runtime.h>
#include <cuda_bf16.h>
#include <cstdint>

#define N_NODES 100000
#define N_EDGES 600000
#define N_GRAPHS 512
#define DIM 128
#define N_LAYERS 3
#define BN_EPS 1e-5f

// ---------------- scratch (device globals; no allocation allowed) ----------
__device__ __align__(16) float g_AGG[(size_t)N_NODES * DIM];
__device__ __align__(16) float g_T[(size_t)N_NODES * DIM];
__device__ float g_S1[DIM], g_Q1[DIM], g_S2[DIM], g_Q2[DIM];
__device__ int g_gstart[N_GRAPHS + 1];
// W fragments, interleaved {hi0,hi1,lo0,lo1}: [mat][kb 8][nb 16][lane 32][4]
__device__ __align__(16) uint32_t g_Wfrag[6 * 16384];

// ---------------- helpers ----------------------------------------------------
__device__ __forceinline__ uint32_t pack_bf16x2(float f0, float f1) {
    __nv_bfloat162 h = __floats2bfloat162_rn(f0, f1);
    return *reinterpret_cast<uint32_t*>(&h);
}
__device__ __forceinline__ void split2(float2 v, uint32_t& hi, uint32_t& lo) {
    __nv_bfloat16 h0 = __float2bfloat16_rn(v.x);
    __nv_bfloat16 h1 = __float2bfloat16_rn(v.y);
    float l0 = v.x - __bfloat162float(h0);
    float l1 = v.y - __bfloat162float(h1);
    __nv_bfloat162 hp; hp.x = h0; hp.y = h1;
    hi = *reinterpret_cast<uint32_t*>(&hp);
    lo = pack_bf16x2(l0, l1);
}
__device__ __forceinline__ void mma_bf16(float c[4], const uint32_t a[4], uint32_t b0, uint32_t b1) {
    asm volatile(
        "mma.sync.aligned.m16n8k16.row.col.f32.bf16.bf16.f32 "
        "{%0,%1,%2,%3}, {%4,%5,%6,%7}, {%8,%9}, {%0,%1,%2,%3};"
        : "+f"(c[0]), "+f"(c[1]), "+f"(c[2]), "+f"(c[3])
        : "r"(a[0]), "r"(a[1]), "r"(a[2]), "r"(a[3]), "r"(b0), "r"(b1));
}

// ---------------- prep: W split/layout + graph segment bounds ----------------
__global__ void prep_kernel(const float* __restrict__ W1, const float* __restrict__ W2,
                            const int* __restrict__ batch) {
    int idx = blockIdx.x * blockDim.x + threadIdx.x;
    if (idx < 6 * 4096) {
        int mat = idx >> 12;
        int e = idx & 4095;
        int lane = e & 31;
        int nb = (e >> 5) & 15;
        int kb = e >> 9;
        int n = nb * 8 + (lane >> 2);
        const float* W = (mat < 3) ? (W1 + (size_t)mat * 16384)
                                   : (W2 + (size_t)(mat - 3) * 16384);
        uint32_t hi0, lo0, hi1, lo1;
        int k0 = kb * 16 + (lane & 3) * 2;
        split2(make_float2(W[k0 * 128 + n], W[(k0 + 1) * 128 + n]), hi0, lo0);
        int k1 = k0 + 8;
        split2(make_float2(W[k1 * 128 + n], W[(k1 + 1) * 128 + n]), hi1, lo1);
        reinterpret_cast<uint4*>(g_Wfrag)[mat * 4096 + e] = make_uint4(hi0, hi1, lo0, lo1);
    }
    if (idx <= N_NODES) {
        int prev = (idx == 0) ? -1 : batch[idx - 1];
        int cur = (idx == N_NODES) ? N_GRAPHS : batch[idx];
        for (int g = prev + 1; g <= cur; g++) g_gstart[g] = idx;
    }
}

// ---------------- aggregation -------------------------------------------------
__global__ void copy_to_agg_kernel(const float* __restrict__ H) {
    int i = blockIdx.x * blockDim.x + threadIdx.x;
    if (i < N_NODES * (DIM / 4))
        reinterpret_cast<float4*>(g_AGG)[i] = reinterpret_cast<const float4*>(H)[i];
}

// AGG[dst] += H[src] — 4 independent edge-chunks per thread for MLP.
// Block 0 also zeroes the BN accumulators for this layer (runs before gemm<1>).
#define SCATTER_WORK (N_EDGES * 32)          // float4 chunks total
#define SCATTER_QTR (SCATTER_WORK / 4)
__global__ void scatter_add_kernel(const float* __restrict__ H,
                                   const int* __restrict__ src,
                                   const int* __restrict__ dst) {
    int idx = blockIdx.x * blockDim.x + threadIdx.x;
    if (blockIdx.x == 0 && threadIdx.x < DIM) {
        g_S1[threadIdx.x] = 0.f; g_Q1[threadIdx.x] = 0.f;
        g_S2[threadIdx.x] = 0.f; g_Q2[threadIdx.x] = 0.f;
    }
    if (idx >= SCATTER_QTR) return;
    const int j = idx & 31;
    int e0 = idx >> 5;
    int e1 = (idx + SCATTER_QTR) >> 5;
    int e2 = (idx + 2 * SCATTER_QTR) >> 5;
    int e3 = (idx + 3 * SCATTER_QTR) >> 5;
    int s0 = __ldg(&src[e0]), d0 = __ldg(&dst[e0]);
    int s1 = __ldg(&src[e1]), d1 = __ldg(&dst[e1]);
    int s2 = __ldg(&src[e2]), d2 = __ldg(&dst[e2]);
    int s3 = __ldg(&src[e3]), d3 = __ldg(&dst[e3]);
    float4 v0 = reinterpret_cast<const float4*>(H)[s0 * 32 + j];
    float4 v1 = reinterpret_cast<const float4*>(H)[s1 * 32 + j];
    float4 v2 = reinterpret_cast<const float4*>(H)[s2 * 32 + j];
    float4 v3 = reinterpret_cast<const float4*>(H)[s3 * 32 + j];
    atomicAdd(reinterpret_cast<float4*>(g_AGG) + d0 * 32 + j, v0);
    atomicAdd(reinterpret_cast<float4*>(g_AGG) + d1 * 32 + j, v1);
    atomicAdd(reinterpret_cast<float4*>(g_AGG) + d2 * 32 + j, v2);
    atomicAdd(reinterpret_cast<float4*>(g_AGG) + d3 * 32 + j, v3);
}

// ---------------- HMMA GEMM + column stats -----------------------------------
// PHASE 1: T   = AGG @ W + b    (stats -> S1/Q1)
// PHASE 2: AGG = BN1(T) @ W + b (BN1 from S1/Q1 in prologue; stats -> S2/Q2)
// Ping-pong buffers: NEVER in-place. 128x128 block, 8 warps; warp = 32x64
// (rg=wid&3, ch=wid>>2). __launch_bounds__(256,2) pins regs <=128 -> 2 CTAs/SM
// (R15 let regs float to 129 -> 1 CTA/SM -> 75us; R14 measured 53.6us at 102).
#define SMB_BFRAG 0
#define SMB_BIAS 65536
#define SMB_SCL 66048
#define SMB_SHF 66560
#define SMB_SS 67072
#define SMB_SQ 67584
#define SMB_TOTAL 68096

template <int PHASE>
__global__ void __launch_bounds__(256, 2) gemm_mma_kernel(int mat,
                                                          const float* __restrict__ bias,
                                                          const float* __restrict__ bn_g,
                                                          const float* __restrict__ bn_b) {
    const float* A   = (PHASE == 1) ? g_AGG : g_T;
    float*       Out = (PHASE == 1) ? g_T : g_AGG;
    float*       Sg  = (PHASE == 1) ? g_S1 : g_S2;
    float*       Qg  = (PHASE == 1) ? g_Q1 : g_Q2;

    extern __shared__ __align__(16) char smem[];
    uint32_t* sBf  = reinterpret_cast<uint32_t*>(smem + SMB_BFRAG);
    float* sBias = reinterpret_cast<float*>(smem + SMB_BIAS);
    float* sScl  = reinterpret_cast<float*>(smem + SMB_SCL);
    float* sShf  = reinterpret_cast<float*>(smem + SMB_SHF);
    float* sS    = reinterpret_cast<float*>(smem + SMB_SS);
    float* sQ    = reinterpret_cast<float*>(smem + SMB_SQ);

    const int tid = threadIdx.x;
    const int wid = tid >> 5;
    const int lane = tid & 31;
    const int qrow = lane >> 2;
    const int qk = (lane & 3) * 2;
    const int rg = wid & 3;          // row group: 32 rows
    const int ch = wid >> 2;         // column half (0/1)
    const int row0 = blockIdx.x * 128;

    {
        const uint4* wf = reinterpret_cast<const uint4*>(g_Wfrag + mat * 16384);
        uint4* bf = reinterpret_cast<uint4*>(sBf);
#pragma unroll
        for (int i = 0; i < 16; i++) {
            int idx = tid + i * 256;
            bf[idx] = wf[idx];
        }
    }
    if (tid < DIM) {
        sBias[tid] = bias[tid];
        sS[tid] = 0.f; sQ[tid] = 0.f;
        if (PHASE == 2) {
            const float invN = 1.0f / (float)N_NODES;
            float m = g_S1[tid] * invN;
            float v = fmaxf(g_Q1[tid] * invN - m * m, 0.f);
            float sc = rsqrtf(v + BN_EPS) * bn_g[tid];
            sScl[tid] = sc;
            sShf[tid] = bn_b[tid] - m * sc;
        }
    }
    __syncthreads();

    const int rbase = row0 + rg * 32 + qrow;
    const int r0 = rbase, r1 = rbase + 8, r2 = rbase + 16, r3 = rbase + 24;
    const bool v0 = (r0 < N_NODES), v1 = (r1 < N_NODES);
    const bool v2 = (r2 < N_NODES), v3 = (r3 < N_NODES);
    const float* a0p = A + (size_t)r0 * DIM;
    const float* a1p = A + (size_t)r1 * DIM;
    const float* a2p = A + (size_t)r2 * DIM;
    const float* a3p = A + (size_t)r3 * DIM;

    float c0[8][4], c1[8][4];
#pragma unroll
    for (int nb = 0; nb < 8; nb++) {
#pragma unroll
        for (int q = 0; q < 4; q++) { c0[nb][q] = 0.f; c1[nb][q] = 0.f; }
    }

    const float2 FZ = make_float2(0.f, 0.f);
#pragma unroll
    for (int kb = 0; kb < 8; kb++) {
        const int cidx = kb * 16 + qk;
        float2 x00 = FZ, x01 = FZ, x10 = FZ, x11 = FZ;
        float2 x20 = FZ, x21 = FZ, x30 = FZ, x31 = FZ;
        if (v0) { x00 = *reinterpret_cast<const float2*>(a0p + cidx);
                  x01 = *reinterpret_cast<const float2*>(a0p + cidx + 8); }
        if (v1) { x10 = *reinterpret_cast<const float2*>(a1p + cidx);
                  x11 = *reinterpret_cast<const float2*>(a1p + cidx + 8); }
        if (v2) { x20 = *reinterpret_cast<const float2*>(a2p + cidx);
                  x21 = *reinterpret_cast<const float2*>(a2p + cidx + 8); }
        if (v3) { x30 = *reinterpret_cast<const float2*>(a3p + cidx);
                  x31 = *reinterpret_cast<const float2*>(a3p + cidx + 8); }
        if (PHASE == 2) {
            const float s0_ = sScl[cidx],     h0_ = sShf[cidx];
            const float s1_ = sScl[cidx + 1], h1_ = sShf[cidx + 1];
            const float s8_ = sScl[cidx + 8], h8_ = sShf[cidx + 8];
            const float s9_ = sScl[cidx + 9], h9_ = sShf[cidx + 9];
            x00.x = fmaf(x00.x, s0_, h0_); x00.y = fmaf(x00.y, s1_, h1_);
            x01.x = fmaf(x01.x, s8_, h8_); x01.y = fmaf(x01.y, s9_, h9_);
            x10.x = fmaf(x10.x, s0_, h0_); x10.y = fmaf(x10.y, s1_, h1_);
            x11.x = fmaf(x11.x, s8_, h8_); x11.y = fmaf(x11.y, s9_, h9_);
            x20.x = fmaf(x20.x, s0_, h0_); x20.y = fmaf(x20.y, s1_, h1_);
            x21.x = fmaf(x21.x, s8_, h8_); x21.y = fmaf(x21.y, s9_, h9_);
            x30.x = fmaf(x30.x, s0_, h0_); x30.y = fmaf(x30.y, s1_, h1_);
            x31.x = fmaf(x31.x, s8_, h8_); x31.y = fmaf(x31.y, s9_, h9_);
        }
        uint32_t ahi0[4], alo0[4], ahi1[4], alo1[4];
        split2(x00, ahi0[0], alo0[0]);
        split2(x10, ahi0[1], alo0[1]);
        split2(x01, ahi0[2], alo0[2]);
        split2(x11, ahi0[3], alo0[3]);
        split2(x20, ahi1[0], alo1[0]);
        split2(x30, ahi1[1], alo1[1]);
        split2(x21, ahi1[2], alo1[2]);
        split2(x31, ahi1[3], alo1[3]);

#pragma unroll
        for (int nb = 0; nb < 8; nb++) {
            const int nbg = ch * 8 + nb;
            const uint4 b = *reinterpret_cast<const uint4*>(&sBf[((kb * 16 + nbg) * 32 + lane) * 4]);
            mma_bf16(c0[nb], ahi0, b.x, b.y);
            mma_bf16(c0[nb], ahi0, b.z, b.w);
            mma_bf16(c0[nb], alo0, b.x, b.y);
            mma_bf16(c1[nb], ahi1, b.x, b.y);
            mma_bf16(c1[nb], ahi1, b.z, b.w);
            mma_bf16(c1[nb], alo1, b.x, b.y);
        }
    }

    // ---- epilogue: bias + store + column stats ----
#pragma unroll
    for (int nb = 0; nb < 8; nb++) {
        const int cn = (ch * 8 + nb) * 8 + qk;
        const float b0 = sBias[cn], b1 = sBias[cn + 1];
        float o00 = v0 ? (c0[nb][0] + b0) : 0.f;
        float o01 = v0 ? (c0[nb][1] + b1) : 0.f;
        float o10 = v1 ? (c0[nb][2] + b0) : 0.f;
        float o11 = v1 ? (c0[nb][3] + b1) : 0.f;
        float o20 = v2 ? (c1[nb][0] + b0) : 0.f;
        float o21 = v2 ? (c1[nb][1] + b1) : 0.f;
        float o30 = v3 ? (c1[nb][2] + b0) : 0.f;
        float o31 = v3 ? (c1[nb][3] + b1) : 0.f;
        if (v0) *reinterpret_cast<float2*>(Out + (size_t)r0 * DIM + cn) = make_float2(o00, o01);
        if (v1) *reinterpret_cast<float2*>(Out + (size_t)r1 * DIM + cn) = make_float2(o10, o11);
        if (v2) *reinterpret_cast<float2*>(Out + (size_t)r2 * DIM + cn) = make_float2(o20, o21);
        if (v3) *reinterpret_cast<float2*>(Out + (size_t)r3 * DIM + cn) = make_float2(o30, o31);
        float s0 = o00 + o10 + o20 + o30;
        float s1 = o01 + o11 + o21 + o31;
        float q0 = o00 * o00 + o10 * o10 + o20 * o20 + o30 * o30;
        float q1 = o01 * o01 + o11 * o11 + o21 * o21 + o31 * o31;
#pragma unroll
        for (int off = 4; off < 32; off <<= 1) {
            s0 += __shfl_down_sync(0xFFFFFFFF, s0, off);
            s1 += __shfl_down_sync(0xFFFFFFFF, s1, off);
            q0 += __shfl_down_sync(0xFFFFFFFF, q0, off);
            q1 += __shfl_down_sync(0xFFFFFFFF, q1, off);
        }
        if (lane < 4) {
            atomicAdd(&sS[cn], s0);
            atomicAdd(&sS[cn + 1], s1);
            atomicAdd(&sQ[cn], q0);
            atomicAdd(&sQ[cn + 1], q1);
        }
    }
    __syncthreads();
    if (tid < DIM) { atomicAdd(&Sg[tid], sS[tid]); atomicAdd(&Qg[tid], sQ[tid]); }
}

// H = relu(AGG * sc2 + sh2), BN2∘BN3 coefficients computed in-block from S2/Q2.
// If WRITE_AGG also primes g_AGG = H for next layer.
template <bool WRITE_AGG>
__global__ void apply_relu_kernel(float* __restrict__ H,
                                  const float* __restrict__ g2,
                                  const float* __restrict__ go,
                                  const float* __restrict__ bo) {
    __shared__ float sc2[DIM], sh2[DIM];
    if (threadIdx.x < DIM) {
        int t = threadIdx.x;
        const float invN = 1.0f / (float)N_NODES;
        float m = g_S2[t] * invN;
        float v = fmaxf(g_Q2[t] * invN - m * m, 0.f);
        float r2 = rsqrtf(v + BN_EPS);
        float gg = g2[t];
        float vy = gg * gg * v * r2 * r2;            // exact var of BN2 output
        float sc3 = rsqrtf(vy + BN_EPS) * go[t];
        float total = r2 * gg * sc3;
        sc2[t] = total;
        sh2[t] = bo[t] - m * total;
    }
    __syncthreads();
    int i = blockIdx.x * blockDim.x + threadIdx.x;
    if (i >= N_NODES * (DIM / 4)) return;
    int k = (i & 31) * 4;
    float4 v = reinterpret_cast<float4*>(g_AGG)[i];
    v.x = fmaxf(fmaf(v.x, sc2[k + 0], sh2[k + 0]), 0.f);
    v.y = fmaxf(fmaf(v.y, sc2[k + 1], sh2[k + 1]), 0.f);
    v.z = fmaxf(fmaf(v.z, sc2[k + 2], sh2[k + 2]), 0.f);
    v.w = fmaxf(fmaf(v.w, sc2[k + 3], sh2[k + 3]), 0.f);
    reinterpret_cast<float4*>(H)[i] = v;
    if (WRITE_AGG) reinterpret_cast<float4*>(g_AGG)[i] = v;
}

// ---------------- pooling + classifier ---------------------------------------
__global__ void graph_fc_kernel(const float* __restrict__ H,
                                const float* __restrict__ fcW,
                                const float* __restrict__ fcb,
                                float* __restrict__ Gout,
                                float* __restrict__ Cout) {
    int g = blockIdx.x;
    int t = threadIdx.x;
    int beg = g_gstart[g], end = g_gstart[g + 1];
    float s = 0.f;
    for (int r = beg; r < end; r++) s += H[r * DIM + t];
    float cnt = fmaxf((float)(end - beg), 1.0f);
    float ge = s / cnt;
    Gout[g * DIM + t] = ge;
    __shared__ float r0[DIM], r1[DIM];
    r0[t] = ge * fcW[t * 2 + 0];
    r1[t] = ge * fcW[t * 2 + 1];
    __syncthreads();
    for (int sh = 64; sh > 0; sh >>= 1) {
        if (t < sh) { r0[t] += r0[t + sh]; r1[t] += r1[t + sh]; }
        __syncthreads();
    }
    if (t == 0) {
        Cout[g * 2 + 0] = r0[0] + fcb[0];
        Cout[g * 2 + 1] = r1[0] + fcb[1];
    }
}

// ---------------- launcher ---------------------------------------------------
extern "C" void kernel_launch(void* const* d_in, const int* in_sizes, int n_in,
                              void* d_out, int out_size) {
    const float* x     = (const float*)d_in[0];
    const int*   ei    = (const int*)d_in[1];
    const int*   batch = (const int*)d_in[2];
    const float* W1    = (const float*)d_in[3];
    const float* b1    = (const float*)d_in[4];
    const float* g1    = (const float*)d_in[5];
    const float* bt1   = (const float*)d_in[6];
    const float* W2    = (const float*)d_in[7];
    const float* b2    = (const float*)d_in[8];
    const float* g2    = (const float*)d_in[9];
    // d_in[10] (bt2) cancels analytically in BN2∘BN3
    const float* go    = (const float*)d_in[11];
    const float* bo    = (const float*)d_in[12];
    const float* fcW   = (const float*)d_in[13];
    const float* fcb   = (const float*)d_in[14];

    float* out  = (float*)d_out;
    float* Hout = out;
    float* Gout = out + (size_t)N_NODES * DIM;
    float* Cout = Gout + (size_t)N_GRAPHS * DIM;

    const int* src = ei;
    const int* dst = ei + N_EDGES;

    static bool attr_set = false;
    if (!attr_set) {
        cudaFuncSetAttribute(gemm_mma_kernel<1>, cudaFuncAttributeMaxDynamicSharedMemorySize, SMB_TOTAL);
        cudaFuncSetAttribute(gemm_mma_kernel<2>, cudaFuncAttributeMaxDynamicSharedMemorySize, SMB_TOTAL);
        attr_set = true;
    }

    const int nCopyBlocks    = (N_NODES * (DIM / 4)) / 256;      // 12500
    const int nScatterBlocks = (SCATTER_QTR + 255) / 256;        // 18750
    const int nGemmBlocks    = (N_NODES + 127) / 128;            // 782

    prep_kernel<<<(N_NODES + 256) / 256, 256>>>(W1, W2, batch);

    for (int i = 0; i < N_LAYERS; i++) {
        const float* Hin = (i == 0) ? x : Hout;
        if (i == 0) copy_to_agg_kernel<<<nCopyBlocks, 256>>>(Hin);
        scatter_add_kernel<<<nScatterBlocks, 256>>>(Hin, src, dst);
        gemm_mma_kernel<1><<<nGemmBlocks, 256, SMB_TOTAL>>>(i, b1 + i * DIM,
                                                            nullptr, nullptr);
        gemm_mma_kernel<2><<<nGemmBlocks, 256, SMB_TOTAL>>>(i + 3, b2 + i * DIM,
                                                            g1 + i * DIM, bt1 + i * DIM);
        if (i + 1 < N_LAYERS)
            apply_relu_kernel<true><<<nCopyBlocks, 256>>>(Hout, g2 + i * DIM,
                                                          go + i * DIM, bo + i * DIM);
        else
            apply_relu_kernel<false><<<nCopyBlocks, 256>>>(Hout, g2 + i * DIM,
                                                           go + i * DIM, bo + i * DIM);
    }

    graph_fc_kernel<<<N_GRAPHS, 128>>>(Hout, fcW, fcb, Gout, Cout);
}